// round 2
// baseline (speedup 1.0000x reference)
#include <cuda_runtime.h>
#include <cuda_bf16.h>

#define B_  256
#define T_  2048
#define BT  (B_ * T_)

__device__ float g_petT[BT];
__device__ float g_pT[BT];
__device__ float g_wu[BT];
__device__ float g_wl[BT];
__device__ float g_wd[BT];
__device__ float g_params[8 * BT];
__device__ uint2 g_W1p[32 * 32];
__device__ uint2 g_W2p[16 * 8 * 32];
__device__ uint2 g_W3p[4 * 32];

__device__ __forceinline__ float fast_ex2(float x) {
    float r; asm("ex2.approx.f32 %0, %1;" : "=f"(r) : "f"(x)); return r;
}
__device__ __forceinline__ float fast_rcp(float x) {
    float r; asm("rcp.approx.f32 %0, %1;" : "=f"(r) : "f"(x)); return r;
}
__device__ __forceinline__ float sig20(float x) {          // heaviside
    return fast_rcp(1.0f + fast_ex2(-28.8539008f * x));
}
__device__ __forceinline__ float sigm1(float x) {          // plain sigmoid
    return fast_rcp(1.0f + fast_ex2(-1.44269504f * x));
}
__device__ __forceinline__ float tanh_fast(float x) {
    float e = fast_ex2(2.88539008f * x);
    return (e - 1.0f) * fast_rcp(e + 1.0f);
}
__device__ __forceinline__ float clipv(float x) {
    return fminf(fmaxf(x, -100000.0f), 100000.0f);
}
__device__ __forceinline__ unsigned int packbf(float lo, float hi) {
    __nv_bfloat162 v;
    v.x = __float2bfloat16_rn(lo);
    v.y = __float2bfloat16_rn(hi);
    return *reinterpret_cast<unsigned int*>(&v);
}
__device__ __forceinline__ void mma16816(float& c0, float& c1, float& c2, float& c3,
                                         unsigned int a0, unsigned int a1,
                                         unsigned int a2, unsigned int a3,
                                         unsigned int b0, unsigned int b1) {
    asm volatile(
        "mma.sync.aligned.m16n8k16.row.col.f32.bf16.bf16.f32 "
        "{%0,%1,%2,%3},{%4,%5,%6,%7},{%8,%9},{%0,%1,%2,%3};\n"
        : "+f"(c0), "+f"(c1), "+f"(c2), "+f"(c3)
        : "r"(a0), "r"(a1), "r"(a2), "r"(a3), "r"(b0), "r"(b1));
}

// ---- prep: transpose pet/p, pack weights into mma B fragments -----------------
__global__ void prep_kernel(const float* __restrict__ in,
                            const float* __restrict__ w1,
                            const float* __restrict__ w2,
                            const float* __restrict__ w3) {
    int bid = blockIdx.x;
    if (bid < 2048) {
        int r = bid * 256 + threadIdx.x;       // r = b*T + t
        int b = r >> 11;
        int t = r & 2047;
        g_petT[t * B_ + b] = in[r * 20 + 0];
        g_pT  [t * B_ + b] = in[r * 20 + 2];
        return;
    }
    int tid = threadIdx.x;
    for (int i = tid; i < 32 * 32; i += 256) {           // W1 (15x256), k-pad to 16
        int lane = i & 31, nt = i >> 5;
        int g = lane >> 2, tig = lane & 3;
        int n = nt * 8 + g;
        float e0 = w1[(2 * tig) * 256 + n];
        float e1 = w1[(2 * tig + 1) * 256 + n];
        int k2 = 2 * tig + 8, k3 = 2 * tig + 9;
        float e2 = (k2 < 15) ? w1[k2 * 256 + n] : 0.0f;
        float e3 = (k3 < 15) ? w1[k3 * 256 + n] : 0.0f;
        g_W1p[i] = make_uint2(packbf(e0, e1), packbf(e2, e3));
    }
    for (int i = tid; i < 16 * 8 * 32; i += 256) {       // W2 (256x64)
        int lane = i & 31;
        int nt = (i >> 5) & 7;
        int kc = i >> 8;
        int g = lane >> 2, tig = lane & 3;
        int n = nt * 8 + g;
        int k0 = kc * 16 + 2 * tig;
        g_W2p[i] = make_uint2(packbf(w2[k0 * 64 + n], w2[(k0 + 1) * 64 + n]),
                              packbf(w2[(k0 + 8) * 64 + n], w2[(k0 + 9) * 64 + n]));
    }
    for (int i = tid; i < 4 * 32; i += 256) {            // W3 (64x8)
        int lane = i & 31;
        int kc = i >> 5;
        int g = lane >> 2, tig = lane & 3;
        int k0 = kc * 16 + 2 * tig;
        g_W3p[i] = make_uint2(packbf(w3[k0 * 8 + g], w3[(k0 + 1) * 8 + g]),
                              packbf(w3[(k0 + 8) * 8 + g], w3[(k0 + 9) * 8 + g]));
    }
}

// ---- fused: blocks 0,1 = sequential scan ; blocks 2.. = MLP -------------------
__global__ void __launch_bounds__(128)
main_kernel(const float* __restrict__ in,
            const float* __restrict__ b1v,
            const float* __restrict__ b2v,
            const float* __restrict__ b3v) {
    if (blockIdx.x < 2) {
        int b = blockIdx.x * 128 + threadIdx.x;     // basin 0..255
        float wu = 0.0f, wl = 0.0f, wd = 0.0f;
#pragma unroll 4
        for (int t = 0; t < T_; ++t) {
            float pet = g_petT[t * B_ + b];
            float p   = g_pT[t * B_ + b];
            float h1  = sig20(wu - pet);
            float et1 = fmaf(h1, pet - wu, wu);
            float z   = pet - et1;
            float rp  = sig20(z) * z;
            float hw  = sig20(rp - wl);
            float et22 = fmaf(hw, wl - rp, rp);
            float et2  = sig20(rp) * et22;
            float y    = rp - et2;
            float hy   = sig20(y - wd);
            float et33 = fmaf(hy, wd - y, y);
            float et3  = sig20(y) * et33;
            float s1 = p - et1;
            float s2 = s1 - et2;
            float s3 = s2 - et3;
            wu += clipv(s1);
            wl += clipv(s2);
            wd += clipv(s3);
            int o = t * B_ + b;
            g_wu[o] = wu;
            g_wl[o] = wl;
            g_wd[o] = wd;
        }
        return;
    }

    // MLP: 64 rows/block, 4 warps x one m16 tile
    int bi   = blockIdx.x - 2;
    int warp = threadIdx.x >> 5;
    int lane = threadIdx.x & 31;
    int g    = lane >> 2, tig = lane & 3;
    int r0   = bi * 64 + warp * 16 + g;
    int r1   = r0 + 8;

    unsigned int A0, A1, A2, A3;
    {
        const float* q0 = in + r0 * 20 + 5;
        const float* q1 = in + r1 * 20 + 5;
        float x0 = q0[2 * tig],     x1 = q0[2 * tig + 1];
        float y0 = q1[2 * tig],     y1 = q1[2 * tig + 1];
        float x2 = q0[2 * tig + 8];
        float y2 = q1[2 * tig + 8];
        float x3 = (tig < 3) ? q0[2 * tig + 9] : 0.0f;
        float y3 = (tig < 3) ? q1[2 * tig + 9] : 0.0f;
        A0 = packbf(x0, x1); A1 = packbf(y0, y1);
        A2 = packbf(x2, x3); A3 = packbf(y2, y3);
    }

    unsigned int h1a[16][4];
#pragma unroll
    for (int nt = 0; nt < 32; ++nt) {
        uint2 w = g_W1p[nt * 32 + lane];
        float c0 = 0.f, c1 = 0.f, c2 = 0.f, c3 = 0.f;
        mma16816(c0, c1, c2, c3, A0, A1, A2, A3, w.x, w.y);
        int   n0  = nt * 8 + 2 * tig;
        float bb0 = b1v[n0], bb1 = b1v[n0 + 1];
        c0 = tanh_fast(c0 + bb0); c1 = tanh_fast(c1 + bb1);
        c2 = tanh_fast(c2 + bb0); c3 = tanh_fast(c3 + bb1);
        h1a[nt >> 1][(nt & 1) * 2 + 0] = packbf(c0, c1);
        h1a[nt >> 1][(nt & 1) * 2 + 1] = packbf(c2, c3);
    }

    float acc[8][4];
#pragma unroll
    for (int nt = 0; nt < 8; ++nt) { acc[nt][0] = acc[nt][1] = acc[nt][2] = acc[nt][3] = 0.0f; }
#pragma unroll
    for (int kc = 0; kc < 16; ++kc) {
#pragma unroll
        for (int nt = 0; nt < 8; ++nt) {
            uint2 w = g_W2p[(kc * 8 + nt) * 32 + lane];
            mma16816(acc[nt][0], acc[nt][1], acc[nt][2], acc[nt][3],
                     h1a[kc][0], h1a[kc][1], h1a[kc][2], h1a[kc][3], w.x, w.y);
        }
    }
    unsigned int h2a[4][4];
#pragma unroll
    for (int nt = 0; nt < 8; ++nt) {
        int   n0  = nt * 8 + 2 * tig;
        float bb0 = b2v[n0], bb1 = b2v[n0 + 1];
        float c0 = tanh_fast(acc[nt][0] + bb0), c1 = tanh_fast(acc[nt][1] + bb1);
        float c2 = tanh_fast(acc[nt][2] + bb0), c3 = tanh_fast(acc[nt][3] + bb1);
        h2a[nt >> 1][(nt & 1) * 2 + 0] = packbf(c0, c1);
        h2a[nt >> 1][(nt & 1) * 2 + 1] = packbf(c2, c3);
    }

    float p0 = 0.f, p1 = 0.f, p2 = 0.f, p3 = 0.f;
#pragma unroll
    for (int kc = 0; kc < 4; ++kc) {
        uint2 w = g_W3p[kc * 32 + lane];
        mma16816(p0, p1, p2, p3, h2a[kc][0], h2a[kc][1], h2a[kc][2], h2a[kc][3], w.x, w.y);
    }
    int   n0  = 2 * tig;
    float bb0 = b3v[n0], bb1 = b3v[n0 + 1];
    p0 = sigm1(p0 + bb0);
    p1 = sigm1(p1 + bb1);
    p2 = sigm1(p2 + bb0);
    p3 = sigm1(p3 + bb1);
    g_params[n0 * BT + r0]       = p0;
    g_params[(n0 + 1) * BT + r0] = p1;
    g_params[n0 * BT + r1]       = p2;
    g_params[(n0 + 1) * BT + r1] = p3;
}

// ---- final pointwise: runoff + partition (reference's swapped args!) ----------
__global__ void final_kernel(const float* __restrict__ in, float* __restrict__ out) {
    int r = blockIdx.x * 256 + threadIdx.x;     // r = b*T + t
    int b = r >> 11, t = r & 2047;
    int o = t * B_ + b;
    float wu = g_wu[o], wd = g_wd[o];
    float p  = in[r * 20 + 2];
    float wum = g_params[0 * BT + r];
    float wlm = g_params[1 * BT + r];
    float wdm = g_params[2 * BT + r];
    float bb  = g_params[3 * BT + r];
    float cc  = g_params[4 * BT + r];
    float k1  = g_params[5 * BT + r];
    float k2  = g_params[6 * BT + r];
    float k3  = g_params[7 * BT + r];

    // reference calls _runoff(wu, wd, wl, p, wum, wdm, wlm, b, c)
    float wum_s = wum * 19.9f + 0.1f;
    float wlm_s = wdm * 30.0f + 60.0f;   // inner wlm <- outer wdm
    float wdm_s = wlm * 60.0f + 60.0f;   // inner wdm <- outer wlm
    float c_s   = cc * 0.19f + 0.01f;
    float b_s   = bb * 0.3f + 0.1f;
    float wt    = wum_s + wlm_s + wdm_s;
    float iwt   = fast_rcp(wt);
    float u = wu * iwt;                  // inner wu
    float v = wd * iwt;                  // inner wl <- outer wd
    float s = c_s * u * u + b_s * v * v;
    float d = p - s;
    float runoff = sig20(d) * d;

    float k1s = k1 * 0.69f + 0.01f;
    float k2s = k2 * 0.69f + 0.01f;
    float k3s = k3 * 0.89f + 0.01f;
    float sr  = k1s * runoff;
    float itf = k2s * (runoff - sr);
    float bf  = k3s * (runoff - sr - itf);
    out[r] = sr + 0.5f * itf + 0.25f * bf;
}

extern "C" void kernel_launch(void* const* d_in, const int* in_sizes, int n_in,
                              void* d_out, int out_size) {
    const float* in  = (const float*)d_in[0];
    const float* w1  = (const float*)d_in[1];
    const float* b1  = (const float*)d_in[2];
    const float* w2  = (const float*)d_in[3];
    const float* b2  = (const float*)d_in[4];
    const float* w3  = (const float*)d_in[5];
    const float* b3  = (const float*)d_in[6];
    float* out = (float*)d_out;
    prep_kernel<<<2049, 256>>>(in, w1, w2, w3);
    main_kernel<<<8194, 128>>>(in, b1, b2, b3);
    final_kernel<<<2048, 256>>>(in, out);
}

// round 4
// speedup vs baseline: 3.4649x; 3.4649x over previous
#include <cuda_runtime.h>
#include <cuda_bf16.h>

#define B_  256
#define T_  2048
#define BT  (B_ * T_)
#define NBLK 152

__device__ float2 g_pp[BT];          // (pet, p) transposed [t][b]
__device__ float2 g_w[BT];           // (wu, wd) states [t][b]
__device__ float  g_params[BT * 8];  // row-major [r][8]
__device__ uint2  g_W1p[32 * 32];
__device__ uint2  g_W2p[16 * 8 * 32];
__device__ uint2  g_W3p[4 * 32];

__device__ __forceinline__ float tanhA(float x) {
    float r; asm("tanh.approx.f32 %0, %1;" : "=f"(r) : "f"(x)); return r;
}
__device__ __forceinline__ float heav(float x10) {   // h given 10*x already
    return fmaf(0.5f, tanhA(x10), 0.5f);
}
__device__ __forceinline__ float clipv(float x) {
    return fminf(fmaxf(x, -100000.0f), 100000.0f);
}
__device__ __forceinline__ float sigm1(float x) {    // sigmoid(x)=0.5*tanh(x/2)+0.5
    return fmaf(0.5f, tanhA(0.5f * x), 0.5f);
}
__device__ __forceinline__ unsigned int packbf(float lo, float hi) {
    unsigned int r;
    asm("cvt.rn.bf16x2.f32 %0, %1, %2;" : "=r"(r) : "f"(hi), "f"(lo));
    return r;
}
__device__ __forceinline__ void mma16816(float& c0, float& c1, float& c2, float& c3,
                                         unsigned int a0, unsigned int a1,
                                         unsigned int a2, unsigned int a3,
                                         unsigned int b0, unsigned int b1) {
    asm volatile(
        "mma.sync.aligned.m16n8k16.row.col.f32.bf16.bf16.f32 "
        "{%0,%1,%2,%3},{%4,%5,%6,%7},{%8,%9},{%0,%1,%2,%3};\n"
        : "+f"(c0), "+f"(c1), "+f"(c2), "+f"(c3)
        : "r"(a0), "r"(a1), "r"(a2), "r"(a3), "r"(b0), "r"(b1));
}

// ---- prep: transpose pet/p into float2, pack weights into mma B fragments ----
__global__ void prep_kernel(const float* __restrict__ in,
                            const float* __restrict__ w1,
                            const float* __restrict__ w2,
                            const float* __restrict__ w3) {
    int bid = blockIdx.x;
    if (bid < 2048) {
        int r = bid * 256 + threadIdx.x;       // r = b*T + t
        int b = r >> 11;
        int t = r & 2047;
        g_pp[t * B_ + b] = make_float2(in[r * 20 + 0], in[r * 20 + 2]);
        return;
    }
    int tid = threadIdx.x;
    for (int i = tid; i < 32 * 32; i += 256) {           // W1 (15x256), k-pad to 16
        int lane = i & 31, nt = i >> 5;
        int g = lane >> 2, tig = lane & 3;
        int n = nt * 8 + g;
        float e0 = w1[(2 * tig) * 256 + n];
        float e1 = w1[(2 * tig + 1) * 256 + n];
        int k2 = 2 * tig + 8, k3 = 2 * tig + 9;
        float e2 = (k2 < 15) ? w1[k2 * 256 + n] : 0.0f;
        float e3 = (k3 < 15) ? w1[k3 * 256 + n] : 0.0f;
        g_W1p[i] = make_uint2(packbf(e0, e1), packbf(e2, e3));
    }
    for (int i = tid; i < 16 * 8 * 32; i += 256) {       // W2 (256x64)
        int lane = i & 31;
        int nt = (i >> 5) & 7;
        int kc = i >> 8;
        int g = lane >> 2, tig = lane & 3;
        int n = nt * 8 + g;
        int k0 = kc * 16 + 2 * tig;
        g_W2p[i] = make_uint2(packbf(w2[k0 * 64 + n], w2[(k0 + 1) * 64 + n]),
                              packbf(w2[(k0 + 8) * 64 + n], w2[(k0 + 9) * 64 + n]));
    }
    for (int i = tid; i < 4 * 32; i += 256) {            // W3 (64x8)
        int lane = i & 31;
        int kc = i >> 5;
        int g = lane >> 2, tig = lane & 3;
        int k0 = kc * 16 + 2 * tig;
        g_W3p[i] = make_uint2(packbf(w3[k0 * 8 + g], w3[(k0 + 1) * 8 + g]),
                              packbf(w3[(k0 + 8) * 8 + g], w3[(k0 + 9) * 8 + g]));
    }
}

// ---- fused persistent kernel: 1 block/SM -------------------------------------
// blocks 0,1: sequential water-balance scan (isolated SMs)
// blocks 2..NBLK-1: persistent MLP over all 32768 row-tiles
__global__ void __launch_bounds__(256)
main_kernel(const float* __restrict__ in,
            const float* __restrict__ b1v,
            const float* __restrict__ b2v,
            const float* __restrict__ b3v) {
    __shared__ uint2 sW1[32 * 32];
    __shared__ uint2 sW2[16 * 8 * 32];
    __shared__ uint2 sW3[4 * 32];
    __shared__ float sB1[256];
    __shared__ float sB2[64];
    __shared__ float sB3[8];

    if (blockIdx.x < 2) {
        // ================= scan =================
        if (threadIdx.x >= 128) return;
        int b = blockIdx.x * 128 + threadIdx.x;       // 0..255
        float wu = 0.0f, wl = 0.0f, wd = 0.0f;
        float m10wl = 0.0f, m10wd = 0.0f;             // -10*wl, -10*wd
        float2 buf[4];
#pragma unroll
        for (int i = 0; i < 4; ++i) buf[i] = g_pp[i * B_ + b];

        for (int t4 = 0; t4 < T_; t4 += 4) {
#pragma unroll
            for (int j = 0; j < 4; ++j) {
                int t = t4 + j;
                float pet = buf[j].x;
                float p   = buf[j].y;
                if (t + 4 < T_) buf[j] = g_pp[(t + 4) * B_ + b];

                // et1 = pet - h(pet-wu)*(pet-wu)
                float d1  = pet - wu;
                float h1  = heav(10.0f * d1);
                float z   = h1 * d1;                  // pet - et1
                float et1 = pet - z;
                // rp = h(z)*z
                float hz  = heav(10.0f * z);
                float rp  = hz * z;
                // et2 = h(rp) * (rp + h(rp-wl)*(wl-rp))
                float hw  = heav(fmaf(10.0f, rp, m10wl));
                float hrp = heav(10.0f * rp);
                float et2 = hrp * fmaf(hw, wl - rp, rp);
                // et3 = h(y) * (y + h(y-wd)*(wd-y)),  y = rp - et2
                float y   = rp - et2;
                float h3  = heav(fmaf(10.0f, y, m10wd));
                float hy  = heav(10.0f * y);
                float et3 = hy * fmaf(h3, wd - y, y);

                float s1 = p - et1;
                float s2 = s1 - et2;
                float s3 = s2 - et3;
                wu += clipv(s1);
                wl += clipv(s2);
                wd += clipv(s3);
                m10wl = -10.0f * wl;
                m10wd = -10.0f * wd;
                g_w[t * B_ + b] = make_float2(wu, wd);
            }
        }
        return;
    }

    // ================= persistent MLP =================
    for (int i = threadIdx.x; i < 32 * 32; i += 256)     sW1[i] = g_W1p[i];
    for (int i = threadIdx.x; i < 16 * 8 * 32; i += 256) sW2[i] = g_W2p[i];
    for (int i = threadIdx.x; i < 4 * 32; i += 256)      sW3[i] = g_W3p[i];
    if (threadIdx.x < 256) sB1[threadIdx.x] = b1v[threadIdx.x];
    if (threadIdx.x < 64)  sB2[threadIdx.x] = b2v[threadIdx.x];
    if (threadIdx.x < 8)   sB3[threadIdx.x] = b3v[threadIdx.x];
    __syncthreads();

    int warp = threadIdx.x >> 5;
    int lane = threadIdx.x & 31;
    int g    = lane >> 2, tig = lane & 3;
    int wg   = (blockIdx.x - 2) * 8 + warp;

    for (int tile = wg; tile < 32768; tile += (NBLK - 2) * 8) {
        int r0 = tile * 16 + g;
        int r1 = r0 + 8;

        unsigned int A0, A1, A2, A3;
        {
            const float* q0 = in + r0 * 20 + 5;
            const float* q1 = in + r1 * 20 + 5;
            float x0 = q0[2 * tig],     x1 = q0[2 * tig + 1];
            float y0 = q1[2 * tig],     y1 = q1[2 * tig + 1];
            float x2 = q0[2 * tig + 8];
            float y2 = q1[2 * tig + 8];
            float x3 = (tig < 3) ? q0[2 * tig + 9] : 0.0f;
            float y3 = (tig < 3) ? q1[2 * tig + 9] : 0.0f;
            A0 = packbf(x0, x1); A1 = packbf(y0, y1);
            A2 = packbf(x2, x3); A3 = packbf(y2, y3);
        }

        // stage 1: h1 = tanh(attrs @ W1 + b1)
        unsigned int h1a[16][4];
#pragma unroll
        for (int nt = 0; nt < 32; ++nt) {
            uint2 w = sW1[nt * 32 + lane];
            float c0 = 0.f, c1 = 0.f, c2 = 0.f, c3 = 0.f;
            mma16816(c0, c1, c2, c3, A0, A1, A2, A3, w.x, w.y);
            int   n0  = nt * 8 + 2 * tig;
            float bb0 = sB1[n0], bb1 = sB1[n0 + 1];
            c0 = tanhA(c0 + bb0); c1 = tanhA(c1 + bb1);
            c2 = tanhA(c2 + bb0); c3 = tanhA(c3 + bb1);
            h1a[nt >> 1][(nt & 1) * 2 + 0] = packbf(c0, c1);
            h1a[nt >> 1][(nt & 1) * 2 + 1] = packbf(c2, c3);
        }

        // stage 2: h2 = tanh(h1 @ W2 + b2)
        float acc[8][4];
#pragma unroll
        for (int nt = 0; nt < 8; ++nt) { acc[nt][0] = acc[nt][1] = acc[nt][2] = acc[nt][3] = 0.0f; }
#pragma unroll
        for (int kc = 0; kc < 16; ++kc) {
#pragma unroll
            for (int nt = 0; nt < 8; ++nt) {
                uint2 w = sW2[(kc * 8 + nt) * 32 + lane];
                mma16816(acc[nt][0], acc[nt][1], acc[nt][2], acc[nt][3],
                         h1a[kc][0], h1a[kc][1], h1a[kc][2], h1a[kc][3], w.x, w.y);
            }
        }
        unsigned int h2a[4][4];
#pragma unroll
        for (int nt = 0; nt < 8; ++nt) {
            int   n0  = nt * 8 + 2 * tig;
            float bb0 = sB2[n0], bb1 = sB2[n0 + 1];
            float c0 = tanhA(acc[nt][0] + bb0), c1 = tanhA(acc[nt][1] + bb1);
            float c2 = tanhA(acc[nt][2] + bb0), c3 = tanhA(acc[nt][3] + bb1);
            h2a[nt >> 1][(nt & 1) * 2 + 0] = packbf(c0, c1);
            h2a[nt >> 1][(nt & 1) * 2 + 1] = packbf(c2, c3);
        }

        // stage 3: params = sigmoid(h2 @ W3 + b3)
        float p0 = 0.f, p1 = 0.f, p2 = 0.f, p3 = 0.f;
#pragma unroll
        for (int kc = 0; kc < 4; ++kc) {
            uint2 w = sW3[kc * 32 + lane];
            mma16816(p0, p1, p2, p3, h2a[kc][0], h2a[kc][1], h2a[kc][2], h2a[kc][3], w.x, w.y);
        }
        int   n0  = 2 * tig;
        float bb0 = sB3[n0], bb1 = sB3[n0 + 1];
        p0 = sigm1(p0 + bb0);
        p1 = sigm1(p1 + bb1);
        p2 = sigm1(p2 + bb0);
        p3 = sigm1(p3 + bb1);
        *reinterpret_cast<float2*>(&g_params[r0 * 8 + n0]) = make_float2(p0, p1);
        *reinterpret_cast<float2*>(&g_params[r1 * 8 + n0]) = make_float2(p2, p3);
    }
}

// ---- final pointwise: runoff + partition (reference's swapped args!) ----------
__global__ void final_kernel(const float* __restrict__ in, float* __restrict__ out) {
    int r = blockIdx.x * 256 + threadIdx.x;     // r = b*T + t
    int b = r >> 11, t = r & 2047;
    float2 w = g_w[t * B_ + b];
    float wu = w.x, wd = w.y;
    float p  = in[r * 20 + 2];
    float4 q0 = *reinterpret_cast<const float4*>(&g_params[r * 8]);
    float4 q1 = *reinterpret_cast<const float4*>(&g_params[r * 8 + 4]);
    float wum = q0.x, wlm = q0.y, wdm = q0.z, bb = q0.w;
    float cc  = q1.x, k1 = q1.y, k2 = q1.z, k3 = q1.w;

    // reference calls _runoff(wu, wd, wl, p, wum, wdm, wlm, b, c)
    float wum_s = wum * 19.9f + 0.1f;
    float wlm_s = wdm * 30.0f + 60.0f;   // inner wlm <- outer wdm
    float wdm_s = wlm * 60.0f + 60.0f;   // inner wdm <- outer wlm
    float c_s   = cc * 0.19f + 0.01f;
    float b_s   = bb * 0.3f + 0.1f;
    float wt    = wum_s + wlm_s + wdm_s;
    float iwt   = __frcp_rn(wt);
    float u = wu * iwt;                  // inner wu
    float v = wd * iwt;                  // inner wl <- outer wd
    float s = c_s * u * u + b_s * v * v;
    float d = p - s;
    float runoff = heav(10.0f * d) * d;

    float k1s = k1 * 0.69f + 0.01f;
    float k2s = k2 * 0.69f + 0.01f;
    float k3s = k3 * 0.89f + 0.01f;
    float sr  = k1s * runoff;
    float itf = k2s * (runoff - sr);
    float bf  = k3s * (runoff - sr - itf);
    out[r] = sr + 0.5f * itf + 0.25f * bf;
}

extern "C" void kernel_launch(void* const* d_in, const int* in_sizes, int n_in,
                              void* d_out, int out_size) {
    const float* in  = (const float*)d_in[0];
    const float* w1  = (const float*)d_in[1];
    const float* b1  = (const float*)d_in[2];
    const float* w2  = (const float*)d_in[3];
    const float* b2  = (const float*)d_in[4];
    const float* w3  = (const float*)d_in[5];
    const float* b3  = (const float*)d_in[6];
    float* out = (float*)d_out;
    prep_kernel<<<2049, 256>>>(in, w1, w2, w3);
    main_kernel<<<NBLK, 256>>>(in, b1, b2, b3);
    final_kernel<<<2048, 256>>>(in, out);
}